// round 13
// baseline (speedup 1.0000x reference)
#include <cuda_runtime.h>

#define N_NODES 10000
#define IN_CH   128
#define OUT_CH  64
#define NSTEP   16
#define E_EDGES 320000
#define K_SEL   (E_EDGES/2)
#define NB      40
#define NP      20
#define NTH     192
#define CAND_CAP 65536
#define EB      1250        // E_EDGES / 256 exactly

// ---------------- device scratch ----------------
__device__ float         g_beta[N_NODES*NSTEP];
__device__ float         g_mean_beta[N_NODES];
__device__ float         g_val[N_NODES*OUT_CH];
__device__ float         g_Weff[IN_CH*16];
__device__ float         g_beff[16];
__device__ unsigned int  g_keys[E_EDGES];
__device__ unsigned char g_flags[E_EDGES];
__device__ unsigned int  g_hist16[65536];
__device__ unsigned int  g_chunk[64];
__device__ int           g_srcCnt[N_NODES];
__device__ int           g_srcBase[N_NODES];
__device__ int           g_srcCur[N_NODES];
__device__ int           g_sDst[K_SEL];
__device__ float         g_sEw[K_SEL];
__device__ unsigned int  g_candK[CAND_CAP];
__device__ int           g_candE[CAND_CAP];
__device__ int           g_cand_cnt;
__device__ unsigned int  g_B;
__device__ int           g_R;
__device__ unsigned int  g_done1;
__device__ unsigned int  g_done2;

__device__ __forceinline__ unsigned int fxform(float f) {
    unsigned int u = __float_as_uint(f);
    return (u & 0x80000000u) ? ~u : (u | 0x80000000u);
}

// ---- packed fp32x2 helpers ----
__device__ __forceinline__ void fma2(unsigned long long& d,
                                     unsigned long long a, unsigned long long b) {
    asm("fma.rn.f32x2 %0, %1, %2, %0;" : "+l"(d) : "l"(a), "l"(b));
}
__device__ __forceinline__ unsigned long long pack2(float v) {
    unsigned long long r;
    asm("mov.b64 %0, {%1, %1};" : "=l"(r) : "f"(v));
    return r;
}
__device__ __forceinline__ float2 unpack2(unsigned long long v) {
    float2 f;
    asm("mov.b64 {%0, %1}, %2;" : "=f"(f.x), "=f"(f.y) : "l"(v));
    return f;
}

// ---------------- 1. weff ----------------
__global__ void weff_kernel(const float* __restrict__ Wi,
                            const float* __restrict__ bi,
                            const float* __restrict__ p_t) {
    int t = blockIdx.x * blockDim.x + threadIdx.x;
    if (t < IN_CH*16) {
        int c = t >> 4, s = t & 15;
        const float* w = Wi + c*512 + s*32 + 16;
        const float* p = p_t + s*16;
        float sum = 0.f;
        #pragma unroll
        for (int k = 0; k < 16; k++) sum = fmaf(w[k], p[k], sum);
        g_Weff[c*16 + s] = sum;
    }
    if (t < 16) {
        const float* b = bi + t*32 + 16;
        const float* p = p_t + t*16;
        float sum = 0.f;
        #pragma unroll
        for (int k = 0; k < 16; k++) sum = fmaf(b[k], p[k], sum);
        g_beff[t] = sum;
    }
}

// ---------------- 2. node GEMM: f32x2 + coalesced float2 weights + prefetch ----------------
__global__ __launch_bounds__(NTH) void node_kernel(
    const float* __restrict__ x,
    const float* __restrict__ Wv, const float* __restrict__ bv,
    const float* __restrict__ Wi, const float* __restrict__ bi,
    const float* __restrict__ mw)
{
    __shared__ ulonglong2 xsQ[NP][64];   // 20KB
    __shared__ float      mwS[NB][16];
    __shared__ float      effS[NB][16];
    __shared__ float      betaS[NB][17];

    const int tid   = threadIdx.x;
    const int node0 = blockIdx.x * NB;   // 250 * 40 = 10000
    const unsigned FULL = 0xFFFFFFFFu;

    {
        float* xf = reinterpret_cast<float*>(xsQ);
        for (int idx = tid; idx < NB*64; idx += NTH) {
            int n = idx >> 6, k2 = idx & 63;
            float2 v = reinterpret_cast<const float2*>(x)[(node0 + n)*64 + k2];
            int base = (n >> 1)*256 + k2*4 + (n & 1);
            xf[base]     = v.x;
            xf[base + 2] = v.y;
        }
    }
    for (int idx = tid; idx < NB*16; idx += NTH) {
        int n = idx >> 4, k = idx & 15;
        mwS[n][k] = mw[(node0 + n)*16 + k];
    }
    __syncthreads();

    // thread tid<168 owns adjacent effective columns (2tid, 2tid+1) -> one float2 stream
    const bool active = (tid < 168);
    const float2* wp;
    int wst;
    {
        int c0 = 2*tid;
        if (c0 < 256)      { wp = reinterpret_cast<const float2*>(Wi + (c0 >> 4)*32 + (c0 & 15)); wst = 256; }
        else if (c0 < 320) { wp = reinterpret_cast<const float2*>(Wv + (c0 - 256));               wst = 32; }
        else if (c0 < 336) { wp = reinterpret_cast<const float2*>(g_Weff + (c0 - 320));           wst = 8; }
        else               { wp = reinterpret_cast<const float2*>(Wi);                            wst = 0; }
    }

    unsigned long long a0[NP], a1[NP];
    #pragma unroll
    for (int j = 0; j < NP; j++) { a0[j] = 0ull; a1[j] = 0ull; }

    if (active) {
        float2 r0 = wp[0], r1 = wp[wst];
        wp += 2*wst;
        #pragma unroll 2
        for (int k2 = 0; k2 < 64; k2++) {
            float2 n0, n1;
            if (k2 < 63) { n0 = wp[0]; n1 = wp[wst]; wp += 2*wst; }
            unsigned long long wA0 = pack2(r0.x);  // col c0, row 2k2
            unsigned long long wB0 = pack2(r0.y);  // col c1, row 2k2
            unsigned long long wA1 = pack2(r1.x);  // col c0, row 2k2+1
            unsigned long long wB1 = pack2(r1.y);  // col c1, row 2k2+1
            #pragma unroll
            for (int j = 0; j < NP; j++) {
                ulonglong2 q = xsQ[j][k2];
                fma2(a0[j], q.x, wA0);
                fma2(a0[j], q.y, wA1);
                fma2(a1[j], q.x, wB0);
                fma2(a1[j], q.y, wB1);
            }
            r0 = n0; r1 = n1;
        }
    }

    // epilogue part 1
    if (tid >= 128 && tid < 160) {
        int vc = tid - 128;
        float b0v = bv[2*vc], b1v = bv[2*vc + 1];
        #pragma unroll
        for (int j = 0; j < NP; j++) {
            float2 u0 = unpack2(a0[j]);
            float2 u1 = unpack2(a1[j]);
            float v00 = u0.x + b0v, v01 = u1.x + b1v;
            float v10 = u0.y + b0v, v11 = u1.y + b1v;
            reinterpret_cast<float2*>(g_val)[(node0 + 2*j)*32 + vc] =
                make_float2(v00 > 0.f ? v00 : 0.f, v01 > 0.f ? v01 : 0.f);
            reinterpret_cast<float2*>(g_val)[(node0 + 2*j + 1)*32 + vc] =
                make_float2(v10 > 0.f ? v10 : 0.f, v11 > 0.f ? v11 : 0.f);
        }
    } else if (tid >= 160 && tid < 168) {
        int s0 = 2*(tid - 160), s1 = s0 + 1;
        #pragma unroll
        for (int j = 0; j < NP; j++) {
            float2 u0 = unpack2(a0[j]);
            float2 u1 = unpack2(a1[j]);
            effS[2*j][s0]     = u0.x;  effS[2*j + 1][s0] = u0.y;
            effS[2*j][s1]     = u1.x;  effS[2*j + 1][s1] = u1.y;
        }
    }
    __syncthreads();

    // epilogue part 2: beta via 8-lane butterfly
    if (tid < 128) {
        int s  = tid >> 3;
        int kp = (tid & 7)*2;
        float b0 = bi[s*32 + kp], b1 = bi[s*32 + kp + 1];
        float beffv = g_beff[s];
        #pragma unroll
        for (int j = 0; j < NP; j++) {
            float2 u0 = unpack2(a0[j]);
            float2 u1 = unpack2(a1[j]);
            int n0 = 2*j, n1 = 2*j + 1;
            float c0v = (u0.x + b0)*mwS[n0][kp] + (u1.x + b1)*mwS[n0][kp + 1];
            float c1v = (u0.y + b0)*mwS[n1][kp] + (u1.y + b1)*mwS[n1][kp + 1];
            c0v += __shfl_xor_sync(FULL, c0v, 1);
            c0v += __shfl_xor_sync(FULL, c0v, 2);
            c0v += __shfl_xor_sync(FULL, c0v, 4);
            c1v += __shfl_xor_sync(FULL, c1v, 1);
            c1v += __shfl_xor_sync(FULL, c1v, 2);
            c1v += __shfl_xor_sync(FULL, c1v, 4);
            if ((tid & 7) == 0) {
                betaS[n0][s] = (c0v + effS[n0][s] + beffv) * (1.0f/32.0f);
                betaS[n1][s] = (c1v + effS[n1][s] + beffv) * (1.0f/32.0f);
            }
        }
    }
    __syncthreads();

    for (int idx = tid; idx < NB*16; idx += NTH) {
        int n = idx >> 4, s = idx & 15;
        g_beta[(node0 + n)*NSTEP + s] = betaS[n][s];
    }
    if (tid < NB) {
        float s = 0.f;
        #pragma unroll
        for (int k = 0; k < NSTEP; k++) s += betaS[tid][k];
        g_mean_beta[node0 + tid] = s * (1.0f/NSTEP);
    }
}

// ---------------- 3. keys + hist + chunk sums; last block runs threshold scan ----------------
__global__ void keyhist_kernel(const int* __restrict__ ei, const float* __restrict__ ew) {
    int e = blockIdx.x * blockDim.x + threadIdx.x;   // grid exact: e < E_EDGES always
    if (e < N_NODES) g_srcCnt[e] = 0;
    if (e == 0) g_cand_cnt = 0;
    int lane = threadIdx.x & 31;
    {
        int dst = ei[E_EDGES + e];
        float s = ew[e] * g_mean_beta[dst];
        s += 0.0f;                                 // -0 -> +0
        unsigned int k = fxform(s);
        g_keys[e] = k;
        unsigned int bin = k >> 16;
        unsigned int m = __match_any_sync(0xFFFFFFFFu, bin);
        if (lane == __ffs(m) - 1) atomicAdd(&g_hist16[bin], __popc(m));
        unsigned int ch = bin >> 10;
        unsigned int m2 = __match_any_sync(0xFFFFFFFFu, ch);
        if (lane == __ffs(m2) - 1) atomicAdd(&g_chunk[ch], __popc(m2));
    }

    // ---- last-done block performs the threshold scan ----
    __shared__ unsigned int s_isLast;
    __syncthreads();
    if (threadIdx.x == 0) {
        __threadfence();
        s_isLast = (atomicAdd(&g_done1, 1u) == gridDim.x - 1) ? 1u : 0u;
    }
    __syncthreads();
    if (!s_isLast) return;
    if (threadIdx.x == 0) g_done1 = 0;

    __shared__ unsigned int s_chunk[64];
    __shared__ unsigned int s_w[8];
    __shared__ unsigned int s_wA[8];
    __shared__ int          s_cs;
    __shared__ unsigned int s_ca;
    int t = threadIdx.x, w = t >> 5;
    if (t < 64) s_chunk[t] = __ldcg(&g_chunk[t]);
    __syncthreads();
    if (t == 0) {
        unsigned int cum = 0; int cs = 0;
        for (int c = 63; c >= 0; c--) {
            unsigned int s = s_chunk[c];
            if (cum + s >= (unsigned)K_SEL) { cs = c; break; }
            cum += s;
        }
        s_cs = cs; s_ca = cum;
    }
    __syncthreads();
    int cs = s_cs;
    unsigned int ca = s_ca;

    unsigned int v[4];
    #pragma unroll
    for (int i = 0; i < 4; i++) v[i] = __ldcg(&g_hist16[cs*1024 + t*4 + i]);
    unsigned int tsum = v[0] + v[1] + v[2] + v[3];
    unsigned int suf = tsum;
    #pragma unroll
    for (int off = 1; off < 32; off <<= 1) {
        unsigned int t2 = __shfl_down_sync(0xFFFFFFFFu, suf, off);
        if (lane + off < 32) suf += t2;
    }
    if (lane == 0) s_w[w] = suf;
    __syncthreads();
    if (t == 0) {
        unsigned int run = 0;
        for (int wq = 7; wq >= 0; wq--) { s_wA[wq] = run; run += s_w[wq]; }
    }
    __syncthreads();
    unsigned int suffFromT = suf + s_wA[w];       // sum of tsum over threads >= t
    unsigned int aboveT = ca + suffFromT - tsum;  // strictly above this thread's 4 bins
    unsigned int after = 0;
    #pragma unroll
    for (int i = 3; i >= 0; i--) {
        unsigned int above = aboveT + after;
        if (above < (unsigned)K_SEL && above + v[i] >= (unsigned)K_SEL) {
            g_B = (unsigned)(cs*1024 + t*4 + i);
            g_R = K_SEL - (int)above;
        }
        after += v[i];
    }
}

// ---------------- 4. flag winners + counts; last block resolves ties + prefix ----------------
__global__ void flagcnt_kernel(const int* __restrict__ ei) {
    int e = blockIdx.x * blockDim.x + threadIdx.x;   // grid exact
    if (e < 65536) g_hist16[e] = 0u;                 // scan done last launch
    if (e < 64)    g_chunk[e]  = 0u;
    {
        unsigned int k = g_keys[e];
        unsigned int B = g_B;
        unsigned int t16 = k >> 16;
        unsigned char f = 0;
        if (t16 > B) {
            f = 1;
            atomicAdd(&g_srcCnt[ei[e]], 1);
        } else if (t16 == B) {
            int p = atomicAdd(&g_cand_cnt, 1);
            if (p < CAND_CAP) { g_candK[p] = k; g_candE[p] = e; }
        }
        g_flags[e] = f;
    }

    // ---- last-done block: resolve ties + exclusive prefix over srcCnt ----
    __shared__ unsigned int s_isLast;
    __syncthreads();
    if (threadIdx.x == 0) {
        __threadfence();
        s_isLast = (atomicAdd(&g_done2, 1u) == gridDim.x - 1) ? 1u : 0u;
    }
    __syncthreads();
    if (!s_isLast) return;
    if (threadIdx.x == 0) g_done2 = 0;

    __shared__ unsigned int s_key[4096];
    __shared__ int          s_idx[4096];
    __shared__ unsigned int s_ts[8];
    __shared__ unsigned int s_off[8];
    int t = threadIdx.x, lane = t & 31, w = t >> 5;

    int C = *(volatile int*)&g_cand_cnt; if (C > CAND_CAP) C = CAND_CAP;
    int R = *(volatile int*)&g_R;
    if (C <= 4096) {
        for (int i = t; i < C; i += 256) { s_key[i] = __ldcg(&g_candK[i]); s_idx[i] = __ldcg(&g_candE[i]); }
        __syncthreads();
        for (int i = t; i < C; i += 256) {
            unsigned int ki = s_key[i]; int xi = s_idx[i];
            int rank = 0;
            for (int j = 0; j < C; j++) {
                unsigned int kj = s_key[j];
                rank += (kj > ki) || (kj == ki && s_idx[j] < xi);
            }
            if (rank < R) {                      // stable: smallest index wins
                g_flags[xi] = 1;
                atomicAdd(&g_srcCnt[ei[xi]], 1);
            }
        }
    } else {                                     // pathological fallback
        for (int i = t; i < C; i += 256) {
            unsigned int ki = __ldcg(&g_candK[i]); int xi = __ldcg(&g_candE[i]);
            int rank = 0;
            for (int j = 0; j < C; j++) {
                unsigned int kj = __ldcg(&g_candK[j]);
                rank += (kj > ki) || (kj == ki && __ldcg(&g_candE[j]) < xi);
            }
            if (rank < R) { g_flags[xi] = 1; atomicAdd(&g_srcCnt[ei[xi]], 1); }
        }
    }
    __threadfence();
    __syncthreads();

    // exclusive prefix over 10000 srcCnt, 40 nodes/thread (two-pass)
    int nbase = t * 40;
    unsigned int lsum = 0;
    for (int q = 0; q < 40; q++) {
        int n = nbase + q;
        if (n < N_NODES) lsum += (unsigned)__ldcg(&g_srcCnt[n]);
    }
    unsigned int xI = lsum;
    #pragma unroll
    for (int off = 1; off < 32; off <<= 1) {
        unsigned int up = __shfl_up_sync(0xFFFFFFFFu, xI, off);
        if (lane >= off) xI += up;
    }
    if (lane == 31) s_ts[w] = xI;
    __syncthreads();
    if (t == 0) {
        unsigned int run = 0;
        for (int wq = 0; wq < 8; wq++) { s_off[wq] = run; run += s_ts[wq]; }
    }
    __syncthreads();
    int run = (int)(xI - lsum + s_off[w]);
    for (int q = 0; q < 40; q++) {
        int n = nbase + q;
        if (n < N_NODES) {
            int c = __ldcg(&g_srcCnt[n]);
            g_srcBase[n] = run;
            g_srcCur[n]  = run;
            run += c;
        }
    }
}

// ---------------- 5. scatter ----------------
__global__ void scatter_kernel(const int* __restrict__ ei, const float* __restrict__ ew) {
    int e = blockIdx.x * blockDim.x + threadIdx.x;
    if (e >= E_EDGES) return;
    if (g_flags[e]) {
        int src = ei[e];
        int pos = atomicAdd(&g_srcCur[src], 1);
        g_sDst[pos] = ei[E_EDGES + e];
        g_sEw[pos]  = ew[e];
    }
}

// ---------------- 6. warp-per-src accumulate, packed exp, prefetch ----------------
__global__ __launch_bounds__(1024) void acc_kernel(float* __restrict__ out) {
    const unsigned FULL = 0xFFFFFFFFu;
    int lane = threadIdx.x & 31;
    int gw = (blockIdx.x * blockDim.x + threadIdx.x) >> 5;
    int nwarps = (gridDim.x * blockDim.x) >> 5;
    int sA = lane >> 2;
    int sB = 8 + (lane >> 2);

    for (int src = gw; src < N_NODES; src += nwarps) {
        int cnt  = g_srcCnt[src];
        int base = g_srcBase[src];
        float a0 = 0.f, a1 = 0.f, ds = 0.f;
        int i = 0;
        int nd0 = 0, nd1 = 0; float nw0 = 0.f, nw1 = 0.f;
        if (cnt >= 2) {
            nd0 = __ldcg(&g_sDst[base]);     nd1 = __ldcg(&g_sDst[base + 1]);
            nw0 = __ldcg(&g_sEw[base]);      nw1 = __ldcg(&g_sEw[base + 1]);
        }
        for (; i + 2 <= cnt; i += 2) {
            int d0 = nd0, d1 = nd1;
            float w0 = nw0, w1 = nw1;
            if (i + 4 <= cnt) {
                nd0 = __ldcg(&g_sDst[base + i + 2]); nd1 = __ldcg(&g_sDst[base + i + 3]);
                nw0 = __ldcg(&g_sEw[base + i + 2]);  nw1 = __ldcg(&g_sEw[base + i + 3]);
            }
            // start val gathers early (independent of exp)
            float v00 = g_val[d0*64 + lane];
            float v01 = g_val[d0*64 + 32 + lane];
            float v10 = g_val[d1*64 + lane];
            float v11 = g_val[d1*64 + 32 + lane];
            float bval = (lane < 16) ? g_beta[d0*NSTEP + lane] * w0
                                     : g_beta[d1*NSTEP + (lane - 16)] * w1;
            float ex = __expf(bval);
            float e00 = __shfl_sync(FULL, ex, sA);
            float e01 = __shfl_sync(FULL, ex, sB);
            float e10 = __shfl_sync(FULL, ex, 16 + sA);
            float e11 = __shfl_sync(FULL, ex, 16 + sB);
            a0 = fmaf(e00, v00, a0);
            a1 = fmaf(e01, v01, a1);
            a0 = fmaf(e10, v10, a0);
            a1 = fmaf(e11, v11, a1);
            ds += ex;
        }
        if (i < cnt) {
            int   d0 = __ldcg(&g_sDst[base + i]);
            float w0 = __ldcg(&g_sEw[base + i]);
            float v00 = g_val[d0*64 + lane];
            float v01 = g_val[d0*64 + 32 + lane];
            float ex0 = 0.f;
            if (lane < 16) ex0 = __expf(g_beta[d0*NSTEP + lane] * w0);
            float e00 = __shfl_sync(FULL, ex0, sA);
            float e01 = __shfl_sync(FULL, ex0, sB);
            a0 = fmaf(e00, v00, a0);
            a1 = fmaf(e01, v01, a1);
            ds += ex0;
        }
        float dA = __shfl_sync(FULL, ds, sA) + __shfl_sync(FULL, ds, 16 + sA) + 1e-16f;
        float dB = __shfl_sync(FULL, ds, sB) + __shfl_sync(FULL, ds, 16 + sB) + 1e-16f;
        out[src*64 + lane]      = a0 / dA;
        out[src*64 + 32 + lane] = a1 / dB;
    }
}

// ---------------- launch ----------------
extern "C" void kernel_launch(void* const* d_in, const int* in_sizes, int n_in,
                              void* d_out, int out_size) {
    const float* x   = (const float*)d_in[0];
    const float* p_t = (const float*)d_in[1];
    const int*   ei  = (const int*)  d_in[2];
    const float* ew  = (const float*)d_in[3];
    const float* Wv  = (const float*)d_in[4];
    const float* bv  = (const float*)d_in[5];
    const float* Wi  = (const float*)d_in[6];
    const float* bi  = (const float*)d_in[7];
    const float* mw  = (const float*)d_in[8];
    float* out = (float*)d_out;

    weff_kernel<<<16, 128>>>(Wi, bi, p_t);
    node_kernel<<<N_NODES/NB, NTH>>>(x, Wv, bv, Wi, bi, mw);
    keyhist_kernel<<<EB, 256>>>(ei, ew);
    flagcnt_kernel<<<EB, 256>>>(ei);
    scatter_kernel<<<EB, 256>>>(ei, ew);
    acc_kernel<<<320, 1024>>>(out);
}

// round 14
// speedup vs baseline: 1.0909x; 1.0909x over previous
#include <cuda_runtime.h>

#define N_NODES 10000
#define IN_CH   128
#define OUT_CH  64
#define NSTEP   16
#define E_EDGES 320000
#define K_SEL   (E_EDGES/2)
#define NB      40
#define NP      20
#define NTH     192
#define CAND_CAP 65536
#define EB      1250        // E_EDGES / 256 exactly

// ---------------- device scratch ----------------
__device__ float         g_beta[N_NODES*NSTEP];
__device__ float         g_mean_beta[N_NODES];
__device__ float         g_val[N_NODES*OUT_CH];
__device__ float         g_Weff[IN_CH*16];
__device__ float         g_beff[16];
__device__ unsigned int  g_keys[E_EDGES];
__device__ unsigned char g_flags[E_EDGES];
__device__ unsigned int  g_hist16[65536];
__device__ unsigned int  g_chunk[64];
__device__ int           g_srcCnt[N_NODES];
__device__ int           g_srcBase[N_NODES];
__device__ int           g_srcCur[N_NODES];
__device__ int           g_sDst[K_SEL];
__device__ float         g_sEw[K_SEL];
__device__ unsigned int  g_candK[CAND_CAP];
__device__ int           g_candE[CAND_CAP];
__device__ int           g_cand_cnt;
__device__ unsigned int  g_B;
__device__ int           g_R;
__device__ unsigned int  g_done1;

__device__ __forceinline__ unsigned int fxform(float f) {
    unsigned int u = __float_as_uint(f);
    return (u & 0x80000000u) ? ~u : (u | 0x80000000u);
}

// ---- packed fp32x2 helpers ----
__device__ __forceinline__ void fma2(unsigned long long& d,
                                     unsigned long long a, unsigned long long b) {
    asm("fma.rn.f32x2 %0, %1, %2, %0;" : "+l"(d) : "l"(a), "l"(b));
}
__device__ __forceinline__ unsigned long long pack2(float v) {
    unsigned long long r;
    asm("mov.b64 %0, {%1, %1};" : "=l"(r) : "f"(v));
    return r;
}
__device__ __forceinline__ float2 unpack2(unsigned long long v) {
    float2 f;
    asm("mov.b64 {%0, %1}, %2;" : "=f"(f.x), "=f"(f.y) : "l"(v));
    return f;
}

// ---------------- 1. weff ----------------
__global__ void weff_kernel(const float* __restrict__ Wi,
                            const float* __restrict__ bi,
                            const float* __restrict__ p_t) {
    int t = blockIdx.x * blockDim.x + threadIdx.x;
    if (t < IN_CH*16) {
        int c = t >> 4, s = t & 15;
        const float* w = Wi + c*512 + s*32 + 16;
        const float* p = p_t + s*16;
        float sum = 0.f;
        #pragma unroll
        for (int k = 0; k < 16; k++) sum = fmaf(w[k], p[k], sum);
        g_Weff[c*16 + s] = sum;
    }
    if (t < 16) {
        const float* b = bi + t*32 + 16;
        const float* p = p_t + t*16;
        float sum = 0.f;
        #pragma unroll
        for (int k = 0; k < 16; k++) sum = fmaf(b[k], p[k], sum);
        g_beff[t] = sum;
    }
}

// ---------------- 2. node GEMM: f32x2 + coalesced float2 weights + prefetch ----------------
__global__ __launch_bounds__(NTH) void node_kernel(
    const float* __restrict__ x,
    const float* __restrict__ Wv, const float* __restrict__ bv,
    const float* __restrict__ Wi, const float* __restrict__ bi,
    const float* __restrict__ mw)
{
    __shared__ ulonglong2 xsQ[NP][64];   // 20KB
    __shared__ float      mwS[NB][16];
    __shared__ float      effS[NB][16];
    __shared__ float      betaS[NB][17];

    const int tid   = threadIdx.x;
    const int node0 = blockIdx.x * NB;   // 250 * 40 = 10000
    const unsigned FULL = 0xFFFFFFFFu;

    {
        float* xf = reinterpret_cast<float*>(xsQ);
        for (int idx = tid; idx < NB*64; idx += NTH) {
            int n = idx >> 6, k2 = idx & 63;
            float2 v = reinterpret_cast<const float2*>(x)[(node0 + n)*64 + k2];
            int base = (n >> 1)*256 + k2*4 + (n & 1);
            xf[base]     = v.x;
            xf[base + 2] = v.y;
        }
    }
    for (int idx = tid; idx < NB*16; idx += NTH) {
        int n = idx >> 4, k = idx & 15;
        mwS[n][k] = mw[(node0 + n)*16 + k];
    }
    __syncthreads();

    const bool active = (tid < 168);
    const float2* wp;
    int wst;
    {
        int c0 = 2*tid;
        if (c0 < 256)      { wp = reinterpret_cast<const float2*>(Wi + (c0 >> 4)*32 + (c0 & 15)); wst = 256; }
        else if (c0 < 320) { wp = reinterpret_cast<const float2*>(Wv + (c0 - 256));               wst = 32; }
        else if (c0 < 336) { wp = reinterpret_cast<const float2*>(g_Weff + (c0 - 320));           wst = 8; }
        else               { wp = reinterpret_cast<const float2*>(Wi);                            wst = 0; }
    }

    unsigned long long a0[NP], a1[NP];
    #pragma unroll
    for (int j = 0; j < NP; j++) { a0[j] = 0ull; a1[j] = 0ull; }

    if (active) {
        float2 r0 = wp[0], r1 = wp[wst];
        wp += 2*wst;
        #pragma unroll 2
        for (int k2 = 0; k2 < 64; k2++) {
            float2 n0, n1;
            if (k2 < 63) { n0 = wp[0]; n1 = wp[wst]; wp += 2*wst; }
            unsigned long long wA0 = pack2(r0.x);
            unsigned long long wB0 = pack2(r0.y);
            unsigned long long wA1 = pack2(r1.x);
            unsigned long long wB1 = pack2(r1.y);
            #pragma unroll
            for (int j = 0; j < NP; j++) {
                ulonglong2 q = xsQ[j][k2];
                fma2(a0[j], q.x, wA0);
                fma2(a0[j], q.y, wA1);
                fma2(a1[j], q.x, wB0);
                fma2(a1[j], q.y, wB1);
            }
            r0 = n0; r1 = n1;
        }
    }

    if (tid >= 128 && tid < 160) {
        int vc = tid - 128;
        float b0v = bv[2*vc], b1v = bv[2*vc + 1];
        #pragma unroll
        for (int j = 0; j < NP; j++) {
            float2 u0 = unpack2(a0[j]);
            float2 u1 = unpack2(a1[j]);
            float v00 = u0.x + b0v, v01 = u1.x + b1v;
            float v10 = u0.y + b0v, v11 = u1.y + b1v;
            reinterpret_cast<float2*>(g_val)[(node0 + 2*j)*32 + vc] =
                make_float2(v00 > 0.f ? v00 : 0.f, v01 > 0.f ? v01 : 0.f);
            reinterpret_cast<float2*>(g_val)[(node0 + 2*j + 1)*32 + vc] =
                make_float2(v10 > 0.f ? v10 : 0.f, v11 > 0.f ? v11 : 0.f);
        }
    } else if (tid >= 160 && tid < 168) {
        int s0 = 2*(tid - 160), s1 = s0 + 1;
        #pragma unroll
        for (int j = 0; j < NP; j++) {
            float2 u0 = unpack2(a0[j]);
            float2 u1 = unpack2(a1[j]);
            effS[2*j][s0]     = u0.x;  effS[2*j + 1][s0] = u0.y;
            effS[2*j][s1]     = u1.x;  effS[2*j + 1][s1] = u1.y;
        }
    }
    __syncthreads();

    if (tid < 128) {
        int s  = tid >> 3;
        int kp = (tid & 7)*2;
        float b0 = bi[s*32 + kp], b1 = bi[s*32 + kp + 1];
        float beffv = g_beff[s];
        #pragma unroll
        for (int j = 0; j < NP; j++) {
            float2 u0 = unpack2(a0[j]);
            float2 u1 = unpack2(a1[j]);
            int n0 = 2*j, n1 = 2*j + 1;
            float c0v = (u0.x + b0)*mwS[n0][kp] + (u1.x + b1)*mwS[n0][kp + 1];
            float c1v = (u0.y + b0)*mwS[n1][kp] + (u1.y + b1)*mwS[n1][kp + 1];
            c0v += __shfl_xor_sync(FULL, c0v, 1);
            c0v += __shfl_xor_sync(FULL, c0v, 2);
            c0v += __shfl_xor_sync(FULL, c0v, 4);
            c1v += __shfl_xor_sync(FULL, c1v, 1);
            c1v += __shfl_xor_sync(FULL, c1v, 2);
            c1v += __shfl_xor_sync(FULL, c1v, 4);
            if ((tid & 7) == 0) {
                betaS[n0][s] = (c0v + effS[n0][s] + beffv) * (1.0f/32.0f);
                betaS[n1][s] = (c1v + effS[n1][s] + beffv) * (1.0f/32.0f);
            }
        }
    }
    __syncthreads();

    for (int idx = tid; idx < NB*16; idx += NTH) {
        int n = idx >> 4, s = idx & 15;
        g_beta[(node0 + n)*NSTEP + s] = betaS[n][s];
    }
    if (tid < NB) {
        float s = 0.f;
        #pragma unroll
        for (int k = 0; k < NSTEP; k++) s += betaS[tid][k];
        g_mean_beta[node0 + tid] = s * (1.0f/NSTEP);
    }
}

// ---------------- 3. keys + hist + chunk sums; last block runs threshold scan ----------------
__global__ void keyhist_kernel(const int* __restrict__ ei, const float* __restrict__ ew) {
    int e = blockIdx.x * blockDim.x + threadIdx.x;   // grid exact
    if (e < N_NODES) g_srcCnt[e] = 0;
    if (e == 0) g_cand_cnt = 0;
    int lane = threadIdx.x & 31;
    {
        int dst = ei[E_EDGES + e];
        float s = ew[e] * g_mean_beta[dst];
        s += 0.0f;                                 // -0 -> +0
        unsigned int k = fxform(s);
        g_keys[e] = k;
        unsigned int bin = k >> 16;
        unsigned int m = __match_any_sync(0xFFFFFFFFu, bin);
        if (lane == __ffs(m) - 1) atomicAdd(&g_hist16[bin], __popc(m));
        unsigned int ch = bin >> 10;
        unsigned int m2 = __match_any_sync(0xFFFFFFFFu, ch);
        if (lane == __ffs(m2) - 1) atomicAdd(&g_chunk[ch], __popc(m2));
    }

    __shared__ unsigned int s_isLast;
    __syncthreads();
    if (threadIdx.x == 0) {
        __threadfence();
        s_isLast = (atomicAdd(&g_done1, 1u) == gridDim.x - 1) ? 1u : 0u;
    }
    __syncthreads();
    if (!s_isLast) return;
    if (threadIdx.x == 0) g_done1 = 0;

    __shared__ unsigned int s_chunk[64];
    __shared__ unsigned int s_w[8];
    __shared__ unsigned int s_wA[8];
    __shared__ int          s_cs;
    __shared__ unsigned int s_ca;
    int t = threadIdx.x, w = t >> 5;
    if (t < 64) s_chunk[t] = __ldcg(&g_chunk[t]);
    __syncthreads();
    if (t == 0) {
        unsigned int cum = 0; int cs = 0;
        for (int c = 63; c >= 0; c--) {
            unsigned int s = s_chunk[c];
            if (cum + s >= (unsigned)K_SEL) { cs = c; break; }
            cum += s;
        }
        s_cs = cs; s_ca = cum;
    }
    __syncthreads();
    int cs = s_cs;
    unsigned int ca = s_ca;

    unsigned int v[4];
    #pragma unroll
    for (int i = 0; i < 4; i++) v[i] = __ldcg(&g_hist16[cs*1024 + t*4 + i]);
    unsigned int tsum = v[0] + v[1] + v[2] + v[3];
    unsigned int suf = tsum;
    #pragma unroll
    for (int off = 1; off < 32; off <<= 1) {
        unsigned int t2 = __shfl_down_sync(0xFFFFFFFFu, suf, off);
        if (lane + off < 32) suf += t2;
    }
    if (lane == 0) s_w[w] = suf;
    __syncthreads();
    if (t == 0) {
        unsigned int run = 0;
        for (int wq = 7; wq >= 0; wq--) { s_wA[wq] = run; run += s_w[wq]; }
    }
    __syncthreads();
    unsigned int suffFromT = suf + s_wA[w];
    unsigned int aboveT = ca + suffFromT - tsum;
    unsigned int after = 0;
    #pragma unroll
    for (int i = 3; i >= 0; i--) {
        unsigned int above = aboveT + after;
        if (above < (unsigned)K_SEL && above + v[i] >= (unsigned)K_SEL) {
            g_B = (unsigned)(cs*1024 + t*4 + i);
            g_R = K_SEL - (int)above;
        }
        after += v[i];
    }
}

// ---------------- 4. flag winners + counts (pure; hist zeroed for next run) ----------------
__global__ void flagcnt_kernel(const int* __restrict__ ei) {
    int e = blockIdx.x * blockDim.x + threadIdx.x;
    if (e < 65536) g_hist16[e] = 0u;
    if (e < 64)    g_chunk[e]  = 0u;
    unsigned int k = g_keys[e];
    unsigned int B = g_B;
    unsigned int t16 = k >> 16;
    unsigned char f = 0;
    if (t16 > B) {
        f = 1;
        atomicAdd(&g_srcCnt[ei[e]], 1);
    } else if (t16 == B) {
        int p = atomicAdd(&g_cand_cnt, 1);
        if (p < CAND_CAP) { g_candK[p] = k; g_candE[p] = e; }
    }
    g_flags[e] = f;
}

// ---------------- 5. resolve: radix-narrowed ties + src prefix ----------------
__global__ __launch_bounds__(1024) void resolve_kernel(const int* __restrict__ ei) {
    __shared__ unsigned int s_key[4096];
    __shared__ int          s_idx[4096];
    __shared__ unsigned int s_h[256];
    __shared__ unsigned int s_b1, s_r1, s_b2, s_r2;
    __shared__ unsigned int s_ts[32], s_off[32];

    int t = threadIdx.x, lane = t & 31, w = t >> 5;
    int C = g_cand_cnt; if (C > CAND_CAP) C = CAND_CAP;
    int R = g_R;

    const unsigned int* ck = g_candK;
    const int* cx = g_candE;
    if (C <= 4096) {
        for (int i = t; i < C; i += 1024) { s_key[i] = g_candK[i]; s_idx[i] = g_candE[i]; }
        ck = s_key; cx = s_idx;
    }
    // level 1: histogram bits [8:16)
    if (t < 256) s_h[t] = 0u;
    __syncthreads();
    for (int i = t; i < C; i += 1024) atomicAdd(&s_h[(ck[i] >> 8) & 255u], 1u);
    __syncthreads();
    if (t == 0) {
        unsigned int cum = 0;
        for (int b = 255; b >= 0; b--) {
            unsigned int c = s_h[b];
            if (cum + c >= (unsigned)R) { s_b1 = (unsigned)b; s_r1 = (unsigned)R - cum; break; }
            cum += c;
        }
    }
    __syncthreads();
    unsigned int b1 = s_b1, R1 = s_r1;

    // level 2: winners mid>b1; histogram bits [0:8) among mid==b1
    if (t < 256) s_h[t] = 0u;
    __syncthreads();
    for (int i = t; i < C; i += 1024) {
        unsigned int mid = (ck[i] >> 8) & 255u;
        if (mid > b1) {
            int xi = cx[i];
            g_flags[xi] = 1;
            atomicAdd(&g_srcCnt[ei[xi]], 1);
        } else if (mid == b1) {
            atomicAdd(&s_h[ck[i] & 255u], 1u);
        }
    }
    __syncthreads();
    if (t == 0) {
        unsigned int cum = 0;
        for (int b = 255; b >= 0; b--) {
            unsigned int c = s_h[b];
            if (cum + c >= R1) { s_b2 = (unsigned)b; s_r2 = R1 - cum; break; }
            cum += c;
        }
    }
    __syncthreads();
    unsigned int b2 = s_b2, R2 = s_r2;

    // level 3: winners low>b2; identical-key ties by smallest edge index
    for (int i = t; i < C; i += 1024) {
        unsigned int kk = ck[i];
        if (((kk >> 8) & 255u) == b1) {
            unsigned int low = kk & 255u;
            int xi = cx[i];
            if (low > b2) {
                g_flags[xi] = 1;
                atomicAdd(&g_srcCnt[ei[xi]], 1);
            } else if (low == b2) {
                int rank = 0;
                for (int j = 0; j < C; j++)
                    rank += (ck[j] == kk) && (cx[j] < xi);
                if (rank < (int)R2) {
                    g_flags[xi] = 1;
                    atomicAdd(&g_srcCnt[ei[xi]], 1);
                }
            }
        }
    }
    __threadfence();
    __syncthreads();

    // exclusive prefix over srcCnt, 10 nodes/thread, warp scan
    int nbase = t * 10;
    unsigned int lsum = 0;
    int cnts[10];
    #pragma unroll
    for (int q = 0; q < 10; q++) {
        int n = nbase + q;
        cnts[q] = (n < N_NODES) ? __ldcg(&g_srcCnt[n]) : 0;
        lsum += (unsigned)cnts[q];
    }
    unsigned int xI = lsum;
    #pragma unroll
    for (int off = 1; off < 32; off <<= 1) {
        unsigned int up = __shfl_up_sync(0xFFFFFFFFu, xI, off);
        if (lane >= off) xI += up;
    }
    if (lane == 31) s_ts[w] = xI;
    __syncthreads();
    if (t == 0) {
        unsigned int run = 0;
        for (int wq = 0; wq < 32; wq++) { s_off[wq] = run; run += s_ts[wq]; }
    }
    __syncthreads();
    int run = (int)(xI - lsum + s_off[w]);
    #pragma unroll
    for (int q = 0; q < 10; q++) {
        int n = nbase + q;
        if (n < N_NODES) {
            g_srcBase[n] = run;
            g_srcCur[n]  = run;
            run += cnts[q];
        }
    }
}

// ---------------- 6. scatter ----------------
__global__ void scatter_kernel(const int* __restrict__ ei, const float* __restrict__ ew) {
    int e = blockIdx.x * blockDim.x + threadIdx.x;
    if (e >= E_EDGES) return;
    if (g_flags[e]) {
        int src = ei[e];
        int pos = atomicAdd(&g_srcCur[src], 1);
        g_sDst[pos] = ei[E_EDGES + e];
        g_sEw[pos]  = ew[e];
    }
}

// ---------------- 7. warp-per-src accumulate, packed exp, prefetch ----------------
__global__ __launch_bounds__(1024) void acc_kernel(float* __restrict__ out) {
    const unsigned FULL = 0xFFFFFFFFu;
    int lane = threadIdx.x & 31;
    int gw = (blockIdx.x * blockDim.x + threadIdx.x) >> 5;
    int nwarps = (gridDim.x * blockDim.x) >> 5;
    int sA = lane >> 2;
    int sB = 8 + (lane >> 2);

    for (int src = gw; src < N_NODES; src += nwarps) {
        int cnt  = g_srcCnt[src];
        int base = g_srcBase[src];
        float a0 = 0.f, a1 = 0.f, ds = 0.f;
        int i = 0;
        int nd0 = 0, nd1 = 0; float nw0 = 0.f, nw1 = 0.f;
        if (cnt >= 2) {
            nd0 = __ldcg(&g_sDst[base]);     nd1 = __ldcg(&g_sDst[base + 1]);
            nw0 = __ldcg(&g_sEw[base]);      nw1 = __ldcg(&g_sEw[base + 1]);
        }
        for (; i + 2 <= cnt; i += 2) {
            int d0 = nd0, d1 = nd1;
            float w0 = nw0, w1 = nw1;
            if (i + 4 <= cnt) {
                nd0 = __ldcg(&g_sDst[base + i + 2]); nd1 = __ldcg(&g_sDst[base + i + 3]);
                nw0 = __ldcg(&g_sEw[base + i + 2]);  nw1 = __ldcg(&g_sEw[base + i + 3]);
            }
            float v00 = g_val[d0*64 + lane];
            float v01 = g_val[d0*64 + 32 + lane];
            float v10 = g_val[d1*64 + lane];
            float v11 = g_val[d1*64 + 32 + lane];
            float bval = (lane < 16) ? g_beta[d0*NSTEP + lane] * w0
                                     : g_beta[d1*NSTEP + (lane - 16)] * w1;
            float ex = __expf(bval);
            float e00 = __shfl_sync(FULL, ex, sA);
            float e01 = __shfl_sync(FULL, ex, sB);
            float e10 = __shfl_sync(FULL, ex, 16 + sA);
            float e11 = __shfl_sync(FULL, ex, 16 + sB);
            a0 = fmaf(e00, v00, a0);
            a1 = fmaf(e01, v01, a1);
            a0 = fmaf(e10, v10, a0);
            a1 = fmaf(e11, v11, a1);
            ds += ex;
        }
        if (i < cnt) {
            int   d0 = __ldcg(&g_sDst[base + i]);
            float w0 = __ldcg(&g_sEw[base + i]);
            float v00 = g_val[d0*64 + lane];
            float v01 = g_val[d0*64 + 32 + lane];
            float ex0 = 0.f;
            if (lane < 16) ex0 = __expf(g_beta[d0*NSTEP + lane] * w0);
            float e00 = __shfl_sync(FULL, ex0, sA);
            float e01 = __shfl_sync(FULL, ex0, sB);
            a0 = fmaf(e00, v00, a0);
            a1 = fmaf(e01, v01, a1);
            ds += ex0;
        }
        float dA = __shfl_sync(FULL, ds, sA) + __shfl_sync(FULL, ds, 16 + sA) + 1e-16f;
        float dB = __shfl_sync(FULL, ds, sB) + __shfl_sync(FULL, ds, 16 + sB) + 1e-16f;
        out[src*64 + lane]      = a0 / dA;
        out[src*64 + 32 + lane] = a1 / dB;
    }
}

// ---------------- launch ----------------
extern "C" void kernel_launch(void* const* d_in, const int* in_sizes, int n_in,
                              void* d_out, int out_size) {
    const float* x   = (const float*)d_in[0];
    const float* p_t = (const float*)d_in[1];
    const int*   ei  = (const int*)  d_in[2];
    const float* ew  = (const float*)d_in[3];
    const float* Wv  = (const float*)d_in[4];
    const float* bv  = (const float*)d_in[5];
    const float* Wi  = (const float*)d_in[6];
    const float* bi  = (const float*)d_in[7];
    const float* mw  = (const float*)d_in[8];
    float* out = (float*)d_out;

    weff_kernel<<<16, 128>>>(Wi, bi, p_t);
    node_kernel<<<N_NODES/NB, NTH>>>(x, Wv, bv, Wi, bi, mw);
    keyhist_kernel<<<EB, 256>>>(ei, ew);
    flagcnt_kernel<<<EB, 256>>>(ei);
    resolve_kernel<<<1, 1024>>>(ei);
    scatter_kernel<<<EB, 256>>>(ei, ew);
    acc_kernel<<<320, 1024>>>(out);
}

// round 16
// speedup vs baseline: 1.1521x; 1.0561x over previous
#include <cuda_runtime.h>

#define N_NODES 10000
#define IN_CH   128
#define OUT_CH  64
#define NSTEP   16
#define E_EDGES 320000
#define K_SEL   (E_EDGES/2)
#define NB      34
#define NP      17
#define NTH     192
#define CAND_CAP 65536
#define E4      (E_EDGES/4)          // 80000 vector items
#define EB4     ((E4 + 255)/256)     // 313

// ---------------- device scratch ----------------
__device__ float         g_beta[N_NODES*NSTEP];
__device__ float         g_mean_beta[N_NODES];
__device__ float         g_val[N_NODES*OUT_CH];
__device__ float         g_Weff[IN_CH*16];
__device__ float         g_beff[16];
__device__ unsigned int  g_keys[E_EDGES];
__device__ unsigned char g_flags[E_EDGES];
__device__ unsigned int  g_hist16[65536];
__device__ unsigned int  g_chunk[64];
__device__ int           g_srcCnt[N_NODES];
__device__ int           g_srcBase[N_NODES];
__device__ int           g_srcCur[N_NODES];
__device__ int           g_sDst[K_SEL];
__device__ float         g_sEw[K_SEL];
__device__ unsigned int  g_candK[CAND_CAP];
__device__ int           g_candE[CAND_CAP];
__device__ int           g_cand_cnt;
__device__ unsigned int  g_B;
__device__ int           g_R;
__device__ unsigned int  g_done1;

__device__ __forceinline__ unsigned int fxform(float f) {
    unsigned int u = __float_as_uint(f);
    return (u & 0x80000000u) ? ~u : (u | 0x80000000u);
}

// ---- packed fp32x2 helpers ----
__device__ __forceinline__ void fma2(unsigned long long& d,
                                     unsigned long long a, unsigned long long b) {
    asm("fma.rn.f32x2 %0, %1, %2, %0;" : "+l"(d) : "l"(a), "l"(b));
}
__device__ __forceinline__ unsigned long long pack2(float v) {
    unsigned long long r;
    asm("mov.b64 %0, {%1, %1};" : "=l"(r) : "f"(v));
    return r;
}
__device__ __forceinline__ float2 unpack2(unsigned long long v) {
    float2 f;
    asm("mov.b64 {%0, %1}, %2;" : "=f"(f.x), "=f"(f.y) : "l"(v));
    return f;
}

// ---------------- 1. weff ----------------
__global__ void weff_kernel(const float* __restrict__ Wi,
                            const float* __restrict__ bi,
                            const float* __restrict__ p_t) {
    int t = blockIdx.x * blockDim.x + threadIdx.x;
    if (t < IN_CH*16) {
        int c = t >> 4, s = t & 15;
        const float* w = Wi + c*512 + s*32 + 16;
        const float* p = p_t + s*16;
        float sum = 0.f;
        #pragma unroll
        for (int k = 0; k < 16; k++) sum = fmaf(w[k], p[k], sum);
        g_Weff[c*16 + s] = sum;
    }
    if (t < 16) {
        const float* b = bi + t*32 + 16;
        const float* p = p_t + t*16;
        float sum = 0.f;
        #pragma unroll
        for (int k = 0; k < 16; k++) sum = fmaf(b[k], p[k], sum);
        g_beff[t] = sum;
    }
}

// ---------------- 2. node GEMM: f32x2, coalesced weights, balanced 295-grid ----------------
__global__ __launch_bounds__(NTH) void node_kernel(
    const float* __restrict__ x,
    const float* __restrict__ Wv, const float* __restrict__ bv,
    const float* __restrict__ Wi, const float* __restrict__ bi,
    const float* __restrict__ mw)
{
    __shared__ ulonglong2 xsQ[NP][64];   // 17.4KB
    __shared__ float      mwS[NB][16];
    __shared__ float      effS[NB][16];
    __shared__ float      betaS[NB][17];

    const int tid   = threadIdx.x;
    const int node0 = blockIdx.x * NB;   // 295 blocks, last partial
    const unsigned FULL = 0xFFFFFFFFu;

    {
        float* xf = reinterpret_cast<float*>(xsQ);
        for (int idx = tid; idx < NB*64; idx += NTH) {
            int n = idx >> 6, k2 = idx & 63;
            int nn = node0 + n; if (nn > N_NODES-1) nn = N_NODES-1;
            float2 v = reinterpret_cast<const float2*>(x)[nn*64 + k2];
            int base = (n >> 1)*256 + k2*4 + (n & 1);
            xf[base]     = v.x;
            xf[base + 2] = v.y;
        }
    }
    for (int idx = tid; idx < NB*16; idx += NTH) {
        int n = idx >> 4, k = idx & 15;
        int nn = node0 + n; if (nn > N_NODES-1) nn = N_NODES-1;
        mwS[n][k] = mw[nn*16 + k];
    }
    __syncthreads();

    const bool active = (tid < 168);
    const float2* wp;
    int wst;
    {
        int c0 = 2*tid;
        if (c0 < 256)      { wp = reinterpret_cast<const float2*>(Wi + (c0 >> 4)*32 + (c0 & 15)); wst = 256; }
        else if (c0 < 320) { wp = reinterpret_cast<const float2*>(Wv + (c0 - 256));               wst = 32; }
        else if (c0 < 336) { wp = reinterpret_cast<const float2*>(g_Weff + (c0 - 320));           wst = 8; }
        else               { wp = reinterpret_cast<const float2*>(Wi);                            wst = 0; }
    }

    unsigned long long a0[NP], a1[NP];
    #pragma unroll
    for (int j = 0; j < NP; j++) { a0[j] = 0ull; a1[j] = 0ull; }

    if (active) {
        float2 r0 = wp[0], r1 = wp[wst];
        wp += 2*wst;
        #pragma unroll 2
        for (int k2 = 0; k2 < 64; k2++) {
            float2 n0, n1;
            if (k2 < 63) { n0 = wp[0]; n1 = wp[wst]; wp += 2*wst; }
            unsigned long long wA0 = pack2(r0.x);
            unsigned long long wB0 = pack2(r0.y);
            unsigned long long wA1 = pack2(r1.x);
            unsigned long long wB1 = pack2(r1.y);
            #pragma unroll
            for (int j = 0; j < NP; j++) {
                ulonglong2 q = xsQ[j][k2];
                fma2(a0[j], q.x, wA0);
                fma2(a0[j], q.y, wA1);
                fma2(a1[j], q.x, wB0);
                fma2(a1[j], q.y, wB1);
            }
            r0 = n0; r1 = n1;
        }
    }

    if (tid >= 128 && tid < 160) {
        int vc = tid - 128;
        float b0v = bv[2*vc], b1v = bv[2*vc + 1];
        #pragma unroll
        for (int j = 0; j < NP; j++) {
            float2 u0 = unpack2(a0[j]);
            float2 u1 = unpack2(a1[j]);
            float v00 = u0.x + b0v, v01 = u1.x + b1v;
            float v10 = u0.y + b0v, v11 = u1.y + b1v;
            int n0g = node0 + 2*j, n1g = n0g + 1;
            if (n0g < N_NODES)
                reinterpret_cast<float2*>(g_val)[n0g*32 + vc] =
                    make_float2(v00 > 0.f ? v00 : 0.f, v01 > 0.f ? v01 : 0.f);
            if (n1g < N_NODES)
                reinterpret_cast<float2*>(g_val)[n1g*32 + vc] =
                    make_float2(v10 > 0.f ? v10 : 0.f, v11 > 0.f ? v11 : 0.f);
        }
    } else if (tid >= 160 && tid < 168) {
        int s0 = 2*(tid - 160), s1 = s0 + 1;
        #pragma unroll
        for (int j = 0; j < NP; j++) {
            float2 u0 = unpack2(a0[j]);
            float2 u1 = unpack2(a1[j]);
            effS[2*j][s0]     = u0.x;  effS[2*j + 1][s0] = u0.y;
            effS[2*j][s1]     = u1.x;  effS[2*j + 1][s1] = u1.y;
        }
    }
    __syncthreads();

    if (tid < 128) {
        int s  = tid >> 3;
        int kp = (tid & 7)*2;
        float b0 = bi[s*32 + kp], b1 = bi[s*32 + kp + 1];
        float beffv = g_beff[s];
        #pragma unroll
        for (int j = 0; j < NP; j++) {
            float2 u0 = unpack2(a0[j]);
            float2 u1 = unpack2(a1[j]);
            int n0 = 2*j, n1 = 2*j + 1;
            float c0v = (u0.x + b0)*mwS[n0][kp] + (u1.x + b1)*mwS[n0][kp + 1];
            float c1v = (u0.y + b0)*mwS[n1][kp] + (u1.y + b1)*mwS[n1][kp + 1];
            c0v += __shfl_xor_sync(FULL, c0v, 1);
            c0v += __shfl_xor_sync(FULL, c0v, 2);
            c0v += __shfl_xor_sync(FULL, c0v, 4);
            c1v += __shfl_xor_sync(FULL, c1v, 1);
            c1v += __shfl_xor_sync(FULL, c1v, 2);
            c1v += __shfl_xor_sync(FULL, c1v, 4);
            if ((tid & 7) == 0) {
                betaS[n0][s] = (c0v + effS[n0][s] + beffv) * (1.0f/32.0f);
                betaS[n1][s] = (c1v + effS[n1][s] + beffv) * (1.0f/32.0f);
            }
        }
    }
    __syncthreads();

    for (int idx = tid; idx < NB*16; idx += NTH) {
        int n = idx >> 4, s = idx & 15;
        if (node0 + n < N_NODES)
            g_beta[(node0 + n)*NSTEP + s] = betaS[n][s];
    }
    if (tid < NB && node0 + tid < N_NODES) {
        float s = 0.f;
        #pragma unroll
        for (int k = 0; k < NSTEP; k++) s += betaS[tid][k];
        g_mean_beta[node0 + tid] = s * (1.0f/NSTEP);
    }
}

// ---------------- 3. keys + hist (4 edges/thread); last block runs threshold scan ----------------
__global__ void keyhist_kernel(const int* __restrict__ ei, const float* __restrict__ ew) {
    int idx = blockIdx.x * blockDim.x + threadIdx.x;
    int lane = threadIdx.x & 31;
    if (idx < N_NODES) g_srcCnt[idx] = 0;
    if (idx == 0) g_cand_cnt = 0;
    if (idx < E4) {
        int4   d4 = reinterpret_cast<const int4*>(ei + E_EDGES)[idx];
        float4 w4 = reinterpret_cast<const float4*>(ew)[idx];
        float s0 = w4.x * g_mean_beta[d4.x] + 0.0f;
        float s1 = w4.y * g_mean_beta[d4.y] + 0.0f;
        float s2 = w4.z * g_mean_beta[d4.z] + 0.0f;
        float s3 = w4.w * g_mean_beta[d4.w] + 0.0f;
        uint4 k4 = make_uint4(fxform(s0), fxform(s1), fxform(s2), fxform(s3));
        reinterpret_cast<uint4*>(g_keys)[idx] = k4;
        unsigned int am = __activemask();
        unsigned int ks[4] = {k4.x, k4.y, k4.z, k4.w};
        #pragma unroll
        for (int q = 0; q < 4; q++) {
            unsigned int bin = ks[q] >> 16;
            unsigned int m = __match_any_sync(am, bin);
            if (lane == __ffs(m) - 1) atomicAdd(&g_hist16[bin], __popc(m));
            unsigned int ch = bin >> 10;
            unsigned int m2 = __match_any_sync(am, ch);
            if (lane == __ffs(m2) - 1) atomicAdd(&g_chunk[ch], __popc(m2));
        }
    }

    __shared__ unsigned int s_isLast;
    __syncthreads();
    if (threadIdx.x == 0) {
        __threadfence();
        s_isLast = (atomicAdd(&g_done1, 1u) == gridDim.x - 1) ? 1u : 0u;
    }
    __syncthreads();
    if (!s_isLast) return;
    if (threadIdx.x == 0) g_done1 = 0;

    __shared__ unsigned int s_chunk[64];
    __shared__ unsigned int s_w[8];
    __shared__ unsigned int s_wA[8];
    __shared__ int          s_cs;
    __shared__ unsigned int s_ca;
    int t = threadIdx.x, w = t >> 5;
    if (t < 64) s_chunk[t] = __ldcg(&g_chunk[t]);
    __syncthreads();
    if (t == 0) {
        unsigned int cum = 0; int cs = 0;
        for (int c = 63; c >= 0; c--) {
            unsigned int s = s_chunk[c];
            if (cum + s >= (unsigned)K_SEL) { cs = c; break; }
            cum += s;
        }
        s_cs = cs; s_ca = cum;
    }
    __syncthreads();
    int cs = s_cs;
    unsigned int ca = s_ca;

    unsigned int v[4];
    #pragma unroll
    for (int i = 0; i < 4; i++) v[i] = __ldcg(&g_hist16[cs*1024 + t*4 + i]);
    unsigned int tsum = v[0] + v[1] + v[2] + v[3];
    unsigned int suf = tsum;
    #pragma unroll
    for (int off = 1; off < 32; off <<= 1) {
        unsigned int t2 = __shfl_down_sync(0xFFFFFFFFu, suf, off);
        if (lane + off < 32) suf += t2;
    }
    if (lane == 0) s_w[w] = suf;
    __syncthreads();
    if (t == 0) {
        unsigned int run = 0;
        for (int wq = 7; wq >= 0; wq--) { s_wA[wq] = run; run += s_w[wq]; }
    }
    __syncthreads();
    unsigned int suffFromT = suf + s_wA[w];
    unsigned int aboveT = ca + suffFromT - tsum;
    unsigned int after = 0;
    #pragma unroll
    for (int i = 3; i >= 0; i--) {
        unsigned int above = aboveT + after;
        if (above < (unsigned)K_SEL && above + v[i] >= (unsigned)K_SEL) {
            g_B = (unsigned)(cs*1024 + t*4 + i);
            g_R = K_SEL - (int)above;
        }
        after += v[i];
    }
}

// ---------------- 4. flags + counts, 4 edges/thread ----------------
__global__ void flagcnt_kernel(const int* __restrict__ ei) {
    int idx = blockIdx.x * blockDim.x + threadIdx.x;
    if (idx < 16384)
        reinterpret_cast<uint4*>(g_hist16)[idx] = make_uint4(0u,0u,0u,0u);
    if (idx < 64) g_chunk[idx] = 0u;
    if (idx >= E4) return;

    uint4 k4 = reinterpret_cast<const uint4*>(g_keys)[idx];
    int4  s4 = reinterpret_cast<const int4*>(ei)[idx];
    unsigned int B = g_B;
    unsigned int ks[4] = {k4.x, k4.y, k4.z, k4.w};
    int          ss[4] = {s4.x, s4.y, s4.z, s4.w};
    uchar4 f4 = make_uchar4(0,0,0,0);
    unsigned char* fp = &f4.x;
    int e0 = idx*4;
    #pragma unroll
    for (int q = 0; q < 4; q++) {
        unsigned int t16 = ks[q] >> 16;
        if (t16 > B) {
            fp[q] = 1;
            atomicAdd(&g_srcCnt[ss[q]], 1);
        } else if (t16 == B) {
            int p = atomicAdd(&g_cand_cnt, 1);
            if (p < CAND_CAP) { g_candK[p] = ks[q]; g_candE[p] = e0 + q; }
        }
    }
    reinterpret_cast<uchar4*>(g_flags)[idx] = f4;
}

// ---------------- 5. resolve: radix-narrowed ties + src prefix ----------------
__global__ __launch_bounds__(1024) void resolve_kernel(const int* __restrict__ ei) {
    __shared__ unsigned int s_key[4096];
    __shared__ int          s_idx[4096];
    __shared__ unsigned int s_h[256];
    __shared__ unsigned int s_b1, s_r1, s_b2, s_r2;
    __shared__ unsigned int s_ts[32], s_off[32];

    int t = threadIdx.x, lane = t & 31, w = t >> 5;
    int C = g_cand_cnt; if (C > CAND_CAP) C = CAND_CAP;
    int R = g_R;

    const unsigned int* ck = g_candK;
    const int* cx = g_candE;
    if (C <= 4096) {
        for (int i = t; i < C; i += 1024) { s_key[i] = g_candK[i]; s_idx[i] = g_candE[i]; }
        ck = s_key; cx = s_idx;
    }
    if (t < 256) s_h[t] = 0u;
    __syncthreads();
    for (int i = t; i < C; i += 1024) atomicAdd(&s_h[(ck[i] >> 8) & 255u], 1u);
    __syncthreads();
    if (t == 0) {
        unsigned int cum = 0;
        for (int b = 255; b >= 0; b--) {
            unsigned int c = s_h[b];
            if (cum + c >= (unsigned)R) { s_b1 = (unsigned)b; s_r1 = (unsigned)R - cum; break; }
            cum += c;
        }
    }
    __syncthreads();
    unsigned int b1 = s_b1, R1 = s_r1;

    if (t < 256) s_h[t] = 0u;
    __syncthreads();
    for (int i = t; i < C; i += 1024) {
        unsigned int mid = (ck[i] >> 8) & 255u;
        if (mid > b1) {
            int xi = cx[i];
            g_flags[xi] = 1;
            atomicAdd(&g_srcCnt[ei[xi]], 1);
        } else if (mid == b1) {
            atomicAdd(&s_h[ck[i] & 255u], 1u);
        }
    }
    __syncthreads();
    if (t == 0) {
        unsigned int cum = 0;
        for (int b = 255; b >= 0; b--) {
            unsigned int c = s_h[b];
            if (cum + c >= R1) { s_b2 = (unsigned)b; s_r2 = R1 - cum; break; }
            cum += c;
        }
    }
    __syncthreads();
    unsigned int b2 = s_b2, R2 = s_r2;

    for (int i = t; i < C; i += 1024) {
        unsigned int kk = ck[i];
        if (((kk >> 8) & 255u) == b1) {
            unsigned int low = kk & 255u;
            int xi = cx[i];
            if (low > b2) {
                g_flags[xi] = 1;
                atomicAdd(&g_srcCnt[ei[xi]], 1);
            } else if (low == b2) {
                int rank = 0;
                for (int j = 0; j < C; j++)
                    rank += (ck[j] == kk) && (cx[j] < xi);
                if (rank < (int)R2) {
                    g_flags[xi] = 1;
                    atomicAdd(&g_srcCnt[ei[xi]], 1);
                }
            }
        }
    }
    __threadfence();
    __syncthreads();

    int nbase = t * 10;
    unsigned int lsum = 0;
    int cnts[10];
    #pragma unroll
    for (int q = 0; q < 10; q++) {
        int n = nbase + q;
        cnts[q] = (n < N_NODES) ? __ldcg(&g_srcCnt[n]) : 0;
        lsum += (unsigned)cnts[q];
    }
    unsigned int xI = lsum;
    #pragma unroll
    for (int off = 1; off < 32; off <<= 1) {
        unsigned int up = __shfl_up_sync(0xFFFFFFFFu, xI, off);
        if (lane >= off) xI += up;
    }
    if (lane == 31) s_ts[w] = xI;
    __syncthreads();
    if (t == 0) {
        unsigned int run = 0;
        for (int wq = 0; wq < 32; wq++) { s_off[wq] = run; run += s_ts[wq]; }
    }
    __syncthreads();
    int run = (int)(xI - lsum + s_off[w]);
    #pragma unroll
    for (int q = 0; q < 10; q++) {
        int n = nbase + q;
        if (n < N_NODES) {
            g_srcBase[n] = run;
            g_srcCur[n]  = run;
            run += cnts[q];
        }
    }
}

// ---------------- 6. scatter, 4 edges/thread ----------------
__global__ void scatter_kernel(const int* __restrict__ ei, const float* __restrict__ ew) {
    int idx = blockIdx.x * blockDim.x + threadIdx.x;
    if (idx >= E4) return;
    uchar4 f4 = reinterpret_cast<const uchar4*>(g_flags)[idx];
    if (!(f4.x | f4.y | f4.z | f4.w)) return;
    int4   s4 = reinterpret_cast<const int4*>(ei)[idx];
    int4   d4 = reinterpret_cast<const int4*>(ei + E_EDGES)[idx];
    float4 w4 = reinterpret_cast<const float4*>(ew)[idx];
    const unsigned char* fp = &f4.x;
    const int*   sp = &s4.x;
    const int*   dp = &d4.x;
    const float* wp = &w4.x;
    #pragma unroll
    for (int q = 0; q < 4; q++) {
        if (fp[q]) {
            int pos = atomicAdd(&g_srcCur[sp[q]], 1);
            g_sDst[pos] = dp[q];
            g_sEw[pos]  = wp[q];
        }
    }
}

// ---------------- 7. warp-per-src accumulate, 4-edge unroll, packed exp ----------------
__global__ __launch_bounds__(1024) void acc_kernel(float* __restrict__ out) {
    const unsigned FULL = 0xFFFFFFFFu;
    int lane = threadIdx.x & 31;
    int gw = (blockIdx.x * blockDim.x + threadIdx.x) >> 5;
    int nwarps = (gridDim.x * blockDim.x) >> 5;
    int sA = lane >> 2;
    int sB = 8 + (lane >> 2);

    for (int src = gw; src < N_NODES; src += nwarps) {
        int cnt  = g_srcCnt[src];
        int base = g_srcBase[src];
        float a0 = 0.f, a1 = 0.f, ds = 0.f;
        int i = 0;
        for (; i + 4 <= cnt; i += 4) {
            int   d0 = __ldcg(&g_sDst[base + i]);
            int   d1 = __ldcg(&g_sDst[base + i + 1]);
            int   d2 = __ldcg(&g_sDst[base + i + 2]);
            int   d3 = __ldcg(&g_sDst[base + i + 3]);
            float w0 = __ldcg(&g_sEw[base + i]);
            float w1 = __ldcg(&g_sEw[base + i + 1]);
            float w2 = __ldcg(&g_sEw[base + i + 2]);
            float w3 = __ldcg(&g_sEw[base + i + 3]);
            float v00 = g_val[d0*64 + lane],      v01 = g_val[d0*64 + 32 + lane];
            float v10 = g_val[d1*64 + lane],      v11 = g_val[d1*64 + 32 + lane];
            float v20 = g_val[d2*64 + lane],      v21 = g_val[d2*64 + 32 + lane];
            float v30 = g_val[d3*64 + lane],      v31 = g_val[d3*64 + 32 + lane];
            float bA = (lane < 16) ? g_beta[d0*NSTEP + lane] * w0
                                   : g_beta[d1*NSTEP + (lane - 16)] * w1;
            float bB = (lane < 16) ? g_beta[d2*NSTEP + lane] * w2
                                   : g_beta[d3*NSTEP + (lane - 16)] * w3;
            float exA = __expf(bA);
            float exB = __expf(bB);
            float e00 = __shfl_sync(FULL, exA, sA);
            float e01 = __shfl_sync(FULL, exA, sB);
            float e10 = __shfl_sync(FULL, exA, 16 + sA);
            float e11 = __shfl_sync(FULL, exA, 16 + sB);
            float e20 = __shfl_sync(FULL, exB, sA);
            float e21 = __shfl_sync(FULL, exB, sB);
            float e30 = __shfl_sync(FULL, exB, 16 + sA);
            float e31 = __shfl_sync(FULL, exB, 16 + sB);
            a0 = fmaf(e00, v00, a0);  a1 = fmaf(e01, v01, a1);
            a0 = fmaf(e10, v10, a0);  a1 = fmaf(e11, v11, a1);
            a0 = fmaf(e20, v20, a0);  a1 = fmaf(e21, v21, a1);
            a0 = fmaf(e30, v30, a0);  a1 = fmaf(e31, v31, a1);
            ds += exA + exB;
        }
        for (; i + 2 <= cnt; i += 2) {
            int   d0 = __ldcg(&g_sDst[base + i]);
            int   d1 = __ldcg(&g_sDst[base + i + 1]);
            float w0 = __ldcg(&g_sEw[base + i]);
            float w1 = __ldcg(&g_sEw[base + i + 1]);
            float v00 = g_val[d0*64 + lane], v01 = g_val[d0*64 + 32 + lane];
            float v10 = g_val[d1*64 + lane], v11 = g_val[d1*64 + 32 + lane];
            float bA = (lane < 16) ? g_beta[d0*NSTEP + lane] * w0
                                   : g_beta[d1*NSTEP + (lane - 16)] * w1;
            float exA = __expf(bA);
            float e00 = __shfl_sync(FULL, exA, sA);
            float e01 = __shfl_sync(FULL, exA, sB);
            float e10 = __shfl_sync(FULL, exA, 16 + sA);
            float e11 = __shfl_sync(FULL, exA, 16 + sB);
            a0 = fmaf(e00, v00, a0);  a1 = fmaf(e01, v01, a1);
            a0 = fmaf(e10, v10, a0);  a1 = fmaf(e11, v11, a1);
            ds += exA;
        }
        if (i < cnt) {
            int   d0 = __ldcg(&g_sDst[base + i]);
            float w0 = __ldcg(&g_sEw[base + i]);
            float v00 = g_val[d0*64 + lane], v01 = g_val[d0*64 + 32 + lane];
            float ex0 = 0.f;
            if (lane < 16) ex0 = __expf(g_beta[d0*NSTEP + lane] * w0);
            float e00 = __shfl_sync(FULL, ex0, sA);
            float e01 = __shfl_sync(FULL, ex0, sB);
            a0 = fmaf(e00, v00, a0);
            a1 = fmaf(e01, v01, a1);
            ds += ex0;
        }
        float dA = __shfl_sync(FULL, ds, sA) + __shfl_sync(FULL, ds, 16 + sA) + 1e-16f;
        float dB = __shfl_sync(FULL, ds, sB) + __shfl_sync(FULL, ds, 16 + sB) + 1e-16f;
        out[src*64 + lane]      = a0 / dA;
        out[src*64 + 32 + lane] = a1 / dB;
    }
}

// ---------------- launch ----------------
extern "C" void kernel_launch(void* const* d_in, const int* in_sizes, int n_in,
                              void* d_out, int out_size) {
    const float* x   = (const float*)d_in[0];
    const float* p_t = (const float*)d_in[1];
    const int*   ei  = (const int*)  d_in[2];
    const float* ew  = (const float*)d_in[3];
    const float* Wv  = (const float*)d_in[4];
    const float* bv  = (const float*)d_in[5];
    const float* Wi  = (const float*)d_in[6];
    const float* bi  = (const float*)d_in[7];
    const float* mw  = (const float*)d_in[8];
    float* out = (float*)d_out;

    weff_kernel<<<16, 128>>>(Wi, bi, p_t);
    node_kernel<<<(N_NODES + NB - 1)/NB, NTH>>>(x, Wv, bv, Wi, bi, mw);  // 295
    keyhist_kernel<<<EB4, 256>>>(ei, ew);
    flagcnt_kernel<<<EB4, 256>>>(ei);
    resolve_kernel<<<1, 1024>>>(ei);
    scatter_kernel<<<EB4, 256>>>(ei, ew);
    acc_kernel<<<296, 1024>>>(out);
}

// round 17
// speedup vs baseline: 1.3943x; 1.2102x over previous
#include <cuda_runtime.h>

#define N_NODES 10000
#define IN_CH   128
#define OUT_CH  64
#define NSTEP   16
#define E_EDGES 320000
#define K_SEL   (E_EDGES/2)
#define NB      34
#define NP      17
#define NTH     192
#define CAND_CAP 65536
#define E4      (E_EDGES/4)          // 80000 vector items
#define EB4     ((E4 + 255)/256)     // 313
#define BCAP    128                  // bucket slots per src (Poisson(16) tail; overflow impossible in practice)

// ---------------- device scratch ----------------
__device__ float         g_beta[N_NODES*NSTEP];
__device__ float         g_mean_beta[N_NODES];
__device__ float         g_val[N_NODES*OUT_CH];
__device__ float         g_Weff[IN_CH*16];
__device__ float         g_beff[16];
__device__ unsigned int  g_keys[E_EDGES];
__device__ unsigned int  g_hist16[65536];
__device__ unsigned int  g_chunk[64];
__device__ int           g_srcCnt[N_NODES];
__device__ int2          g_bucket[N_NODES*BCAP];   // (dst, ew-bits) per selected edge, grouped by src
__device__ unsigned int  g_candK[CAND_CAP];
__device__ int           g_candE[CAND_CAP];
__device__ int           g_cand_cnt;
__device__ unsigned int  g_B;
__device__ int           g_R;
__device__ unsigned int  g_done1;

__device__ __forceinline__ unsigned int fxform(float f) {
    unsigned int u = __float_as_uint(f);
    return (u & 0x80000000u) ? ~u : (u | 0x80000000u);
}

// ---- packed fp32x2 helpers ----
__device__ __forceinline__ void fma2(unsigned long long& d,
                                     unsigned long long a, unsigned long long b) {
    asm("fma.rn.f32x2 %0, %1, %2, %0;" : "+l"(d) : "l"(a), "l"(b));
}
__device__ __forceinline__ unsigned long long pack2(float v) {
    unsigned long long r;
    asm("mov.b64 %0, {%1, %1};" : "=l"(r) : "f"(v));
    return r;
}
__device__ __forceinline__ float2 unpack2(unsigned long long v) {
    float2 f;
    asm("mov.b64 {%0, %1}, %2;" : "=f"(f.x), "=f"(f.y) : "l"(v));
    return f;
}

// ---------------- 1. weff ----------------
__global__ void weff_kernel(const float* __restrict__ Wi,
                            const float* __restrict__ bi,
                            const float* __restrict__ p_t) {
    int t = blockIdx.x * blockDim.x + threadIdx.x;
    if (t < IN_CH*16) {
        int c = t >> 4, s = t & 15;
        const float* w = Wi + c*512 + s*32 + 16;
        const float* p = p_t + s*16;
        float sum = 0.f;
        #pragma unroll
        for (int k = 0; k < 16; k++) sum = fmaf(w[k], p[k], sum);
        g_Weff[c*16 + s] = sum;
    }
    if (t < 16) {
        const float* b = bi + t*32 + 16;
        const float* p = p_t + t*16;
        float sum = 0.f;
        #pragma unroll
        for (int k = 0; k < 16; k++) sum = fmaf(b[k], p[k], sum);
        g_beff[t] = sum;
    }
}

// ---------------- 2. node GEMM: f32x2, coalesced weights, balanced 295-grid ----------------
__global__ __launch_bounds__(NTH) void node_kernel(
    const float* __restrict__ x,
    const float* __restrict__ Wv, const float* __restrict__ bv,
    const float* __restrict__ Wi, const float* __restrict__ bi,
    const float* __restrict__ mw)
{
    __shared__ ulonglong2 xsQ[NP][64];   // 17.4KB
    __shared__ float      mwS[NB][16];
    __shared__ float      effS[NB][16];
    __shared__ float      betaS[NB][17];

    const int tid   = threadIdx.x;
    const int node0 = blockIdx.x * NB;   // 295 blocks, last partial
    const unsigned FULL = 0xFFFFFFFFu;

    {
        float* xf = reinterpret_cast<float*>(xsQ);
        for (int idx = tid; idx < NB*64; idx += NTH) {
            int n = idx >> 6, k2 = idx & 63;
            int nn = node0 + n; if (nn > N_NODES-1) nn = N_NODES-1;
            float2 v = reinterpret_cast<const float2*>(x)[nn*64 + k2];
            int base = (n >> 1)*256 + k2*4 + (n & 1);
            xf[base]     = v.x;
            xf[base + 2] = v.y;
        }
    }
    for (int idx = tid; idx < NB*16; idx += NTH) {
        int n = idx >> 4, k = idx & 15;
        int nn = node0 + n; if (nn > N_NODES-1) nn = N_NODES-1;
        mwS[n][k] = mw[nn*16 + k];
    }
    __syncthreads();

    const bool active = (tid < 168);
    const float2* wp;
    int wst;
    {
        int c0 = 2*tid;
        if (c0 < 256)      { wp = reinterpret_cast<const float2*>(Wi + (c0 >> 4)*32 + (c0 & 15)); wst = 256; }
        else if (c0 < 320) { wp = reinterpret_cast<const float2*>(Wv + (c0 - 256));               wst = 32; }
        else if (c0 < 336) { wp = reinterpret_cast<const float2*>(g_Weff + (c0 - 320));           wst = 8; }
        else               { wp = reinterpret_cast<const float2*>(Wi);                            wst = 0; }
    }

    unsigned long long a0[NP], a1[NP];
    #pragma unroll
    for (int j = 0; j < NP; j++) { a0[j] = 0ull; a1[j] = 0ull; }

    if (active) {
        float2 r0 = wp[0], r1 = wp[wst];
        wp += 2*wst;
        #pragma unroll 2
        for (int k2 = 0; k2 < 64; k2++) {
            float2 n0, n1;
            if (k2 < 63) { n0 = wp[0]; n1 = wp[wst]; wp += 2*wst; }
            unsigned long long wA0 = pack2(r0.x);
            unsigned long long wB0 = pack2(r0.y);
            unsigned long long wA1 = pack2(r1.x);
            unsigned long long wB1 = pack2(r1.y);
            #pragma unroll
            for (int j = 0; j < NP; j++) {
                ulonglong2 q = xsQ[j][k2];
                fma2(a0[j], q.x, wA0);
                fma2(a0[j], q.y, wA1);
                fma2(a1[j], q.x, wB0);
                fma2(a1[j], q.y, wB1);
            }
            r0 = n0; r1 = n1;
        }
    }

    if (tid >= 128 && tid < 160) {
        int vc = tid - 128;
        float b0v = bv[2*vc], b1v = bv[2*vc + 1];
        #pragma unroll
        for (int j = 0; j < NP; j++) {
            float2 u0 = unpack2(a0[j]);
            float2 u1 = unpack2(a1[j]);
            float v00 = u0.x + b0v, v01 = u1.x + b1v;
            float v10 = u0.y + b0v, v11 = u1.y + b1v;
            int n0g = node0 + 2*j, n1g = n0g + 1;
            if (n0g < N_NODES)
                reinterpret_cast<float2*>(g_val)[n0g*32 + vc] =
                    make_float2(v00 > 0.f ? v00 : 0.f, v01 > 0.f ? v01 : 0.f);
            if (n1g < N_NODES)
                reinterpret_cast<float2*>(g_val)[n1g*32 + vc] =
                    make_float2(v10 > 0.f ? v10 : 0.f, v11 > 0.f ? v11 : 0.f);
        }
    } else if (tid >= 160 && tid < 168) {
        int s0 = 2*(tid - 160), s1 = s0 + 1;
        #pragma unroll
        for (int j = 0; j < NP; j++) {
            float2 u0 = unpack2(a0[j]);
            float2 u1 = unpack2(a1[j]);
            effS[2*j][s0]     = u0.x;  effS[2*j + 1][s0] = u0.y;
            effS[2*j][s1]     = u1.x;  effS[2*j + 1][s1] = u1.y;
        }
    }
    __syncthreads();

    if (tid < 128) {
        int s  = tid >> 3;
        int kp = (tid & 7)*2;
        float b0 = bi[s*32 + kp], b1 = bi[s*32 + kp + 1];
        float beffv = g_beff[s];
        #pragma unroll
        for (int j = 0; j < NP; j++) {
            float2 u0 = unpack2(a0[j]);
            float2 u1 = unpack2(a1[j]);
            int n0 = 2*j, n1 = 2*j + 1;
            float c0v = (u0.x + b0)*mwS[n0][kp] + (u1.x + b1)*mwS[n0][kp + 1];
            float c1v = (u0.y + b0)*mwS[n1][kp] + (u1.y + b1)*mwS[n1][kp + 1];
            c0v += __shfl_xor_sync(FULL, c0v, 1);
            c0v += __shfl_xor_sync(FULL, c0v, 2);
            c0v += __shfl_xor_sync(FULL, c0v, 4);
            c1v += __shfl_xor_sync(FULL, c1v, 1);
            c1v += __shfl_xor_sync(FULL, c1v, 2);
            c1v += __shfl_xor_sync(FULL, c1v, 4);
            if ((tid & 7) == 0) {
                betaS[n0][s] = (c0v + effS[n0][s] + beffv) * (1.0f/32.0f);
                betaS[n1][s] = (c1v + effS[n1][s] + beffv) * (1.0f/32.0f);
            }
        }
    }
    __syncthreads();

    for (int idx = tid; idx < NB*16; idx += NTH) {
        int n = idx >> 4, s = idx & 15;
        if (node0 + n < N_NODES)
            g_beta[(node0 + n)*NSTEP + s] = betaS[n][s];
    }
    if (tid < NB && node0 + tid < N_NODES) {
        float s = 0.f;
        #pragma unroll
        for (int k = 0; k < NSTEP; k++) s += betaS[tid][k];
        g_mean_beta[node0 + tid] = s * (1.0f/NSTEP);
    }
}

// ---------------- 3. keys + hist (4 edges/thread); last block runs threshold scan ----------------
__global__ void keyhist_kernel(const int* __restrict__ ei, const float* __restrict__ ew) {
    int idx = blockIdx.x * blockDim.x + threadIdx.x;
    int lane = threadIdx.x & 31;
    if (idx < N_NODES) g_srcCnt[idx] = 0;
    if (idx == 0) g_cand_cnt = 0;
    if (idx < E4) {
        int4   d4 = reinterpret_cast<const int4*>(ei + E_EDGES)[idx];
        float4 w4 = reinterpret_cast<const float4*>(ew)[idx];
        float s0 = w4.x * g_mean_beta[d4.x] + 0.0f;
        float s1 = w4.y * g_mean_beta[d4.y] + 0.0f;
        float s2 = w4.z * g_mean_beta[d4.z] + 0.0f;
        float s3 = w4.w * g_mean_beta[d4.w] + 0.0f;
        uint4 k4 = make_uint4(fxform(s0), fxform(s1), fxform(s2), fxform(s3));
        reinterpret_cast<uint4*>(g_keys)[idx] = k4;
        unsigned int am = __activemask();
        unsigned int ks[4] = {k4.x, k4.y, k4.z, k4.w};
        #pragma unroll
        for (int q = 0; q < 4; q++) {
            unsigned int bin = ks[q] >> 16;
            unsigned int m = __match_any_sync(am, bin);
            if (lane == __ffs(m) - 1) atomicAdd(&g_hist16[bin], __popc(m));
            unsigned int ch = bin >> 10;
            unsigned int m2 = __match_any_sync(am, ch);
            if (lane == __ffs(m2) - 1) atomicAdd(&g_chunk[ch], __popc(m2));
        }
    }

    __shared__ unsigned int s_isLast;
    __syncthreads();
    if (threadIdx.x == 0) {
        __threadfence();
        s_isLast = (atomicAdd(&g_done1, 1u) == gridDim.x - 1) ? 1u : 0u;
    }
    __syncthreads();
    if (!s_isLast) return;
    if (threadIdx.x == 0) g_done1 = 0;

    __shared__ unsigned int s_chunk[64];
    __shared__ unsigned int s_w[8];
    __shared__ unsigned int s_wA[8];
    __shared__ int          s_cs;
    __shared__ unsigned int s_ca;
    int t = threadIdx.x, w = t >> 5;
    if (t < 64) s_chunk[t] = __ldcg(&g_chunk[t]);
    __syncthreads();
    if (t == 0) {
        unsigned int cum = 0; int cs = 0;
        for (int c = 63; c >= 0; c--) {
            unsigned int s = s_chunk[c];
            if (cum + s >= (unsigned)K_SEL) { cs = c; break; }
            cum += s;
        }
        s_cs = cs; s_ca = cum;
    }
    __syncthreads();
    int cs = s_cs;
    unsigned int ca = s_ca;

    unsigned int v[4];
    #pragma unroll
    for (int i = 0; i < 4; i++) v[i] = __ldcg(&g_hist16[cs*1024 + t*4 + i]);
    unsigned int tsum = v[0] + v[1] + v[2] + v[3];
    unsigned int suf = tsum;
    #pragma unroll
    for (int off = 1; off < 32; off <<= 1) {
        unsigned int t2 = __shfl_down_sync(0xFFFFFFFFu, suf, off);
        if (lane + off < 32) suf += t2;
    }
    if (lane == 0) s_w[w] = suf;
    __syncthreads();
    if (t == 0) {
        unsigned int run = 0;
        for (int wq = 7; wq >= 0; wq--) { s_wA[wq] = run; run += s_w[wq]; }
    }
    __syncthreads();
    unsigned int suffFromT = suf + s_wA[w];
    unsigned int aboveT = ca + suffFromT - tsum;
    unsigned int after = 0;
    #pragma unroll
    for (int i = 3; i >= 0; i--) {
        unsigned int above = aboveT + after;
        if (above < (unsigned)K_SEL && above + v[i] >= (unsigned)K_SEL) {
            g_B = (unsigned)(cs*1024 + t*4 + i);
            g_R = K_SEL - (int)above;
        }
        after += v[i];
    }
}

// ---------------- 4. flag + DIRECT bucket scatter, 4 edges/thread ----------------
__global__ void flagscat_kernel(const int* __restrict__ ei, const float* __restrict__ ew) {
    int idx = blockIdx.x * blockDim.x + threadIdx.x;
    if (idx < 16384)
        reinterpret_cast<uint4*>(g_hist16)[idx] = make_uint4(0u,0u,0u,0u);
    if (idx < 64) g_chunk[idx] = 0u;
    if (idx >= E4) return;

    uint4  k4 = reinterpret_cast<const uint4*>(g_keys)[idx];
    int4   s4 = reinterpret_cast<const int4*>(ei)[idx];
    int4   d4 = reinterpret_cast<const int4*>(ei + E_EDGES)[idx];
    float4 w4 = reinterpret_cast<const float4*>(ew)[idx];
    unsigned int B = g_B;
    unsigned int ks[4] = {k4.x, k4.y, k4.z, k4.w};
    int          ss[4] = {s4.x, s4.y, s4.z, s4.w};
    int          dd[4] = {d4.x, d4.y, d4.z, d4.w};
    float        ww[4] = {w4.x, w4.y, w4.z, w4.w};
    int e0 = idx*4;
    #pragma unroll
    for (int q = 0; q < 4; q++) {
        unsigned int t16 = ks[q] >> 16;
        if (t16 > B) {
            int pos = atomicAdd(&g_srcCnt[ss[q]], 1);
            if (pos < BCAP)
                g_bucket[ss[q]*BCAP + pos] = make_int2(dd[q], __float_as_int(ww[q]));
        } else if (t16 == B) {
            int p = atomicAdd(&g_cand_cnt, 1);
            if (p < CAND_CAP) { g_candK[p] = ks[q]; g_candE[p] = e0 + q; }
        }
    }
}

// ---------------- 5. resolve: radix-narrowed ties, direct scatter ----------------
__global__ __launch_bounds__(1024) void resolve_kernel(const int* __restrict__ ei,
                                                       const float* __restrict__ ew) {
    __shared__ unsigned int s_key[4096];
    __shared__ int          s_idx[4096];
    __shared__ unsigned int s_h[256];
    __shared__ unsigned int s_b1, s_r1, s_b2, s_r2;

    int t = threadIdx.x;
    int C = g_cand_cnt; if (C > CAND_CAP) C = CAND_CAP;
    int R = g_R;

    const unsigned int* ck = g_candK;
    const int* cx = g_candE;
    if (C <= 4096) {
        for (int i = t; i < C; i += 1024) { s_key[i] = g_candK[i]; s_idx[i] = g_candE[i]; }
        ck = s_key; cx = s_idx;
    }
    if (t < 256) s_h[t] = 0u;
    __syncthreads();
    for (int i = t; i < C; i += 1024) atomicAdd(&s_h[(ck[i] >> 8) & 255u], 1u);
    __syncthreads();
    if (t == 0) {
        unsigned int cum = 0;
        for (int b = 255; b >= 0; b--) {
            unsigned int c = s_h[b];
            if (cum + c >= (unsigned)R) { s_b1 = (unsigned)b; s_r1 = (unsigned)R - cum; break; }
            cum += c;
        }
    }
    __syncthreads();
    unsigned int b1 = s_b1, R1 = s_r1;

    if (t < 256) s_h[t] = 0u;
    __syncthreads();
    for (int i = t; i < C; i += 1024) {
        unsigned int mid = (ck[i] >> 8) & 255u;
        if (mid > b1) {
            int xi = cx[i];
            int src = ei[xi];
            int pos = atomicAdd(&g_srcCnt[src], 1);
            if (pos < BCAP)
                g_bucket[src*BCAP + pos] = make_int2(ei[E_EDGES + xi], __float_as_int(ew[xi]));
        } else if (mid == b1) {
            atomicAdd(&s_h[ck[i] & 255u], 1u);
        }
    }
    __syncthreads();
    if (t == 0) {
        unsigned int cum = 0;
        for (int b = 255; b >= 0; b--) {
            unsigned int c = s_h[b];
            if (cum + c >= R1) { s_b2 = (unsigned)b; s_r2 = R1 - cum; break; }
            cum += c;
        }
    }
    __syncthreads();
    unsigned int b2 = s_b2, R2 = s_r2;

    for (int i = t; i < C; i += 1024) {
        unsigned int kk = ck[i];
        if (((kk >> 8) & 255u) == b1) {
            unsigned int low = kk & 255u;
            int xi = cx[i];
            bool win = false;
            if (low > b2) {
                win = true;
            } else if (low == b2) {
                int rank = 0;
                for (int j = 0; j < C; j++)
                    rank += (ck[j] == kk) && (cx[j] < xi);
                win = (rank < (int)R2);        // stable: smallest edge index wins
            }
            if (win) {
                int src = ei[xi];
                int pos = atomicAdd(&g_srcCnt[src], 1);
                if (pos < BCAP)
                    g_bucket[src*BCAP + pos] = make_int2(ei[E_EDGES + xi], __float_as_int(ew[xi]));
            }
        }
    }
}

// ---------------- 6. warp-per-src accumulate from buckets, packed exp ----------------
__global__ __launch_bounds__(1024) void acc_kernel(float* __restrict__ out) {
    const unsigned FULL = 0xFFFFFFFFu;
    int lane = threadIdx.x & 31;
    int gw = (blockIdx.x * blockDim.x + threadIdx.x) >> 5;
    int nwarps = (gridDim.x * blockDim.x) >> 5;
    int sA = lane >> 2;
    int sB = 8 + (lane >> 2);

    for (int src = gw; src < N_NODES; src += nwarps) {
        int cnt = g_srcCnt[src];
        if (cnt > BCAP) cnt = BCAP;
        const int2* bk = &g_bucket[src*BCAP];
        float a0 = 0.f, a1 = 0.f, ds = 0.f;
        int i = 0;
        for (; i + 4 <= cnt; i += 4) {
            int2 e0 = __ldcg(&bk[i]);
            int2 e1 = __ldcg(&bk[i + 1]);
            int2 e2 = __ldcg(&bk[i + 2]);
            int2 e3 = __ldcg(&bk[i + 3]);
            int d0 = e0.x, d1 = e1.x, d2 = e2.x, d3 = e3.x;
            float w0 = __int_as_float(e0.y), w1 = __int_as_float(e1.y);
            float w2 = __int_as_float(e2.y), w3 = __int_as_float(e3.y);
            float v00 = g_val[d0*64 + lane],      v01 = g_val[d0*64 + 32 + lane];
            float v10 = g_val[d1*64 + lane],      v11 = g_val[d1*64 + 32 + lane];
            float v20 = g_val[d2*64 + lane],      v21 = g_val[d2*64 + 32 + lane];
            float v30 = g_val[d3*64 + lane],      v31 = g_val[d3*64 + 32 + lane];
            float bA = (lane < 16) ? g_beta[d0*NSTEP + lane] * w0
                                   : g_beta[d1*NSTEP + (lane - 16)] * w1;
            float bB = (lane < 16) ? g_beta[d2*NSTEP + lane] * w2
                                   : g_beta[d3*NSTEP + (lane - 16)] * w3;
            float exA = __expf(bA);
            float exB = __expf(bB);
            float e00 = __shfl_sync(FULL, exA, sA);
            float e01 = __shfl_sync(FULL, exA, sB);
            float e10 = __shfl_sync(FULL, exA, 16 + sA);
            float e11 = __shfl_sync(FULL, exA, 16 + sB);
            float e20 = __shfl_sync(FULL, exB, sA);
            float e21 = __shfl_sync(FULL, exB, sB);
            float e30 = __shfl_sync(FULL, exB, 16 + sA);
            float e31 = __shfl_sync(FULL, exB, 16 + sB);
            a0 = fmaf(e00, v00, a0);  a1 = fmaf(e01, v01, a1);
            a0 = fmaf(e10, v10, a0);  a1 = fmaf(e11, v11, a1);
            a0 = fmaf(e20, v20, a0);  a1 = fmaf(e21, v21, a1);
            a0 = fmaf(e30, v30, a0);  a1 = fmaf(e31, v31, a1);
            ds += exA + exB;
        }
        for (; i + 2 <= cnt; i += 2) {
            int2 e0 = __ldcg(&bk[i]);
            int2 e1 = __ldcg(&bk[i + 1]);
            int d0 = e0.x, d1 = e1.x;
            float w0 = __int_as_float(e0.y), w1 = __int_as_float(e1.y);
            float v00 = g_val[d0*64 + lane], v01 = g_val[d0*64 + 32 + lane];
            float v10 = g_val[d1*64 + lane], v11 = g_val[d1*64 + 32 + lane];
            float bA = (lane < 16) ? g_beta[d0*NSTEP + lane] * w0
                                   : g_beta[d1*NSTEP + (lane - 16)] * w1;
            float exA = __expf(bA);
            float e00 = __shfl_sync(FULL, exA, sA);
            float e01 = __shfl_sync(FULL, exA, sB);
            float e10 = __shfl_sync(FULL, exA, 16 + sA);
            float e11 = __shfl_sync(FULL, exA, 16 + sB);
            a0 = fmaf(e00, v00, a0);  a1 = fmaf(e01, v01, a1);
            a0 = fmaf(e10, v10, a0);  a1 = fmaf(e11, v11, a1);
            ds += exA;
        }
        if (i < cnt) {
            int2 e0 = __ldcg(&bk[i]);
            int d0 = e0.x;
            float w0 = __int_as_float(e0.y);
            float v00 = g_val[d0*64 + lane], v01 = g_val[d0*64 + 32 + lane];
            float ex0 = 0.f;
            if (lane < 16) ex0 = __expf(g_beta[d0*NSTEP + lane] * w0);
            float e00 = __shfl_sync(FULL, ex0, sA);
            float e01 = __shfl_sync(FULL, ex0, sB);
            a0 = fmaf(e00, v00, a0);
            a1 = fmaf(e01, v01, a1);
            ds += ex0;
        }
        float dA = __shfl_sync(FULL, ds, sA) + __shfl_sync(FULL, ds, 16 + sA) + 1e-16f;
        float dB = __shfl_sync(FULL, ds, sB) + __shfl_sync(FULL, ds, 16 + sB) + 1e-16f;
        out[src*64 + lane]      = a0 / dA;
        out[src*64 + 32 + lane] = a1 / dB;
    }
}

// ---------------- launch ----------------
extern "C" void kernel_launch(void* const* d_in, const int* in_sizes, int n_in,
                              void* d_out, int out_size) {
    const float* x   = (const float*)d_in[0];
    const float* p_t = (const float*)d_in[1];
    const int*   ei  = (const int*)  d_in[2];
    const float* ew  = (const float*)d_in[3];
    const float* Wv  = (const float*)d_in[4];
    const float* bv  = (const float*)d_in[5];
    const float* Wi  = (const float*)d_in[6];
    const float* bi  = (const float*)d_in[7];
    const float* mw  = (const float*)d_in[8];
    float* out = (float*)d_out;

    weff_kernel<<<16, 128>>>(Wi, bi, p_t);
    node_kernel<<<(N_NODES + NB - 1)/NB, NTH>>>(x, Wv, bv, Wi, bi, mw);  // 295
    keyhist_kernel<<<EB4, 256>>>(ei, ew);
    flagscat_kernel<<<EB4, 256>>>(ei, ew);
    resolve_kernel<<<1, 1024>>>(ei, ew);
    acc_kernel<<<296, 1024>>>(out);
}